// round 3
// baseline (speedup 1.0000x reference)
#include <cuda_runtime.h>

// ---------------- problem constants ----------------
#define BB   4096
#define TT   168
#define NF   32
#define HH   64
#define NT   8
#define HOR  24
#define BT   32          // batch rows per CTA
#define NCTA (BB / BT)   // 128
#define THR  512

// ---------------- scratch (device globals; no allocs allowed) ----------------
__device__ float g_seq0[(size_t)TT * BB * HH];   // layer-0 hidden sequence, time-major
__device__ float g_h0[BB * HH];
__device__ float g_c0[BB * HH];
__device__ float g_h1[BB * HH];
__device__ float g_c1[BB * HH];

// ---------------- packed f32x2 helpers (sm_100+) ----------------
__device__ __forceinline__ unsigned long long pk2(float a) {
    unsigned long long r;
    asm("mov.b64 %0, {%1, %1};" : "=l"(r) : "f"(a));
    return r;
}
__device__ __forceinline__ unsigned long long pk22(float a, float b) {
    unsigned long long r;
    asm("mov.b64 %0, {%1, %2};" : "=l"(r) : "f"(a), "f"(b));
    return r;
}
__device__ __forceinline__ void ffma2(unsigned long long& d, unsigned long long a, unsigned long long b) {
    asm("fma.rn.f32x2 %0, %1, %2, %0;" : "+l"(d) : "l"(a), "l"(b));
}
__device__ __forceinline__ float2 unpk2(unsigned long long v) {
    float2 r;
    asm("mov.b64 {%0, %1}, %2;" : "=f"(r.x), "=f"(r.y) : "l"(v));
    return r;
}

// fast, accurate-enough activations (~1e-6 rel err)
__device__ __forceinline__ float sigf(float x) {
    return __fdividef(1.f, 1.f + __expf(-x));
}
__device__ __forceinline__ float tanhf_(float x) {
    float e = __expf(2.f * x);
    return 1.f - __fdividef(2.f, e + 1.f);
}

// ---------------- GEMM tile, duplicated-input layout ----------------
// sIn : [KDIM][64]  each row value stored twice: sIn[k*64 + 2r] = sIn[k*64 + 2r+1] = v
// sW  : [KDIM][256] gate-interleaved: col' = 4*j + gate
// Thread: 4 rows (rb8 = rb4*2), 1 hidden unit (hb4 = 4*cg) -> acc[rr*2]=(i,f), acc[rr*2+1]=(g,o)
template <int KDIM>
__device__ __forceinline__ void gemm_dup(const float* __restrict__ sIn,
                                         const float* __restrict__ sW,
                                         int rb8, int hb4,
                                         unsigned long long* __restrict__ acc) {
#pragma unroll 8
    for (int k = 0; k < KDIM; ++k) {
        ulonglong2 r01 = *reinterpret_cast<const ulonglong2*>(sIn + k * 64 + rb8);
        ulonglong2 r23 = *reinterpret_cast<const ulonglong2*>(sIn + k * 64 + rb8 + 4);
        ulonglong2 w   = *reinterpret_cast<const ulonglong2*>(sW + k * 256 + hb4);
        ffma2(acc[0], r01.x, w.x); ffma2(acc[1], r01.x, w.y);
        ffma2(acc[2], r01.y, w.x); ffma2(acc[3], r01.y, w.y);
        ffma2(acc[4], r23.x, w.x); ffma2(acc[5], r23.x, w.y);
        ffma2(acc[6], r23.y, w.x); ffma2(acc[7], r23.y, w.y);
    }
}

// ---------------- GEMM tile, plain layout (decoder) ----------------
// sIn : [KDIM][32]
template <int KDIM>
__device__ __forceinline__ void gemm_nd(const float* __restrict__ sIn,
                                        const float* __restrict__ sW,
                                        int rb4, int hb4,
                                        unsigned long long* __restrict__ acc) {
#pragma unroll 8
    for (int k = 0; k < KDIM; ++k) {
        float4 h4 = *reinterpret_cast<const float4*>(sIn + k * BT + rb4);
        ulonglong2 w = *reinterpret_cast<const ulonglong2*>(sW + k * 256 + hb4);
        unsigned long long hx = pk2(h4.x);
        unsigned long long hy = pk2(h4.y);
        unsigned long long hz = pk2(h4.z);
        unsigned long long hw = pk2(h4.w);
        ffma2(acc[0], hx, w.x); ffma2(acc[1], hx, w.y);
        ffma2(acc[2], hy, w.x); ffma2(acc[3], hy, w.y);
        ffma2(acc[4], hz, w.x); ffma2(acc[5], hz, w.y);
        ffma2(acc[6], hw, w.x); ffma2(acc[7], hw, w.y);
    }
}

// LSTM gate math for 4 rows x 1 hidden unit. Biases already in acc init.
__device__ __forceinline__ void lstm_act4(const unsigned long long* __restrict__ acc,
                                          float* __restrict__ cst, float* __restrict__ hv) {
#pragma unroll
    for (int rr = 0; rr < 4; ++rr) {
        float2 iff = unpk2(acc[rr * 2]);
        float2 go  = unpk2(acc[rr * 2 + 1]);
        float iv = sigf(iff.x);
        float fv = sigf(iff.y);
        float gv = tanhf_(go.x);
        float ov = sigf(go.y);
        float c = fv * cst[rr] + iv * gv;
        cst[rr] = c;
        hv[rr] = ov * tanhf_(c);
    }
}

// weight loader: dst[k*256 + (4j+g)] = src[(g*64+j)*K + k]
__device__ __forceinline__ void load_w(float* __restrict__ dst, const float* __restrict__ src,
                                       int K, int tid) {
    for (int idx = tid; idx < K * 256; idx += THR) {
        int k = idx >> 8, c = idx & 255, j = c >> 2, g = c & 3;
        dst[idx] = src[(g * HH + j) * K + k];
    }
}

// ==================== kernel 1: fused 2-layer encoder ====================
__global__ void __launch_bounds__(THR, 1)
k_enc(const float* __restrict__ x,
      const float* __restrict__ W0ih, const float* __restrict__ W0hh,
      const float* __restrict__ b0ih, const float* __restrict__ b0hh,
      const float* __restrict__ W1ih, const float* __restrict__ W1hh,
      const float* __restrict__ b1ih, const float* __restrict__ b1hh) {
    extern __shared__ float sm[];
    float* sWih = sm;                       // 64*256 (phase0 uses 32*256)
    float* sWhh = sWih + HH * 256;          // 64*256
    float* sb   = sWhh + HH * 256;          // 256
    float* sin  = sb + 256;                 // 2 x 64*64 (dup, double-buffered)
    float* shT  = sin + 2 * HH * 64;        // 2 x 64*64 (dup, double-buffered)

    const int tid = threadIdx.x;
    const int rb4 = (tid & 7) * 4;
    const int rb8 = rb4 * 2;
    const int cg  = tid >> 3;       // hidden unit 0..63
    const int hb4 = cg * 4;
    const int b0  = blockIdx.x * BT;
    const int lr  = tid >> 4;       // loader row 0..31

    float cst[4] = {0, 0, 0, 0};
    float hv[4];
    unsigned long long b_if, b_go;
    int buf = 0;

    // =================== phase 0: encoder layer 0 ===================
    load_w(sWih, W0ih, NF, tid);
    load_w(sWhh, W0hh, HH, tid);
    if (tid < 256) {
        int j = tid >> 2, g = tid & 3;
        sb[tid] = b0ih[g * HH + j] + b0hh[g * HH + j];
    }
    for (int i = tid; i < HH * 64; i += THR) shT[i] = 0.f;

    const int lf2 = (tid & 15) * 2;   // 2 features per loader thread
    const float* xb = x + (size_t)(b0 + lr) * (TT * NF) + lf2;
    {
        float2 p = *reinterpret_cast<const float2*>(xb);
        *reinterpret_cast<float2*>(sin + (lf2 + 0) * 64 + lr * 2) = make_float2(p.x, p.x);
        *reinterpret_cast<float2*>(sin + (lf2 + 1) * 64 + lr * 2) = make_float2(p.y, p.y);
    }
    __syncthreads();
    {
        float4 bv = *reinterpret_cast<const float4*>(sb + hb4);
        b_if = pk22(bv.x, bv.y);
        b_go = pk22(bv.z, bv.w);
    }

    for (int t = 0; t < TT; ++t) {
        float2 pn = make_float2(0.f, 0.f);
        if (t + 1 < TT) pn = *reinterpret_cast<const float2*>(xb + (t + 1) * NF);

        unsigned long long acc[8] = {b_if, b_go, b_if, b_go, b_if, b_go, b_if, b_go};
        gemm_dup<NF>(sin + buf * 4096, sWih, rb8, hb4, acc);
        gemm_dup<HH>(shT + buf * 4096, sWhh, rb8, hb4, acc);
        lstm_act4(acc, cst, hv);

        float* sq = g_seq0 + (size_t)t * (BB * HH);
#pragma unroll
        for (int rr = 0; rr < 4; ++rr)
            sq[(size_t)(b0 + rb4 + rr) * HH + cg] = hv[rr];

        int nb = buf ^ 1;
        float* sh_n = shT + nb * 4096;
#pragma unroll
        for (int rr = 0; rr < 4; ++rr)
            *reinterpret_cast<float2*>(sh_n + cg * 64 + (rb4 + rr) * 2) = make_float2(hv[rr], hv[rr]);
        float* sx_n = sin + nb * 4096;
        *reinterpret_cast<float2*>(sx_n + (lf2 + 0) * 64 + lr * 2) = make_float2(pn.x, pn.x);
        *reinterpret_cast<float2*>(sx_n + (lf2 + 1) * 64 + lr * 2) = make_float2(pn.y, pn.y);
        __syncthreads();
        buf = nb;
    }
#pragma unroll
    for (int rr = 0; rr < 4; ++rr) {
        g_h0[(size_t)(b0 + rb4 + rr) * HH + cg] = hv[rr];
        g_c0[(size_t)(b0 + rb4 + rr) * HH + cg] = cst[rr];
    }

    // =================== phase 1: encoder layer 1 ===================
    __syncthreads();
    load_w(sWih, W1ih, HH, tid);
    load_w(sWhh, W1hh, HH, tid);
    if (tid < 256) {
        int j = tid >> 2, g = tid & 3;
        sb[tid] = b1ih[g * HH + j] + b1hh[g * HH + j];
    }
    for (int i = tid; i < HH * 64; i += THR) shT[i] = 0.f;

    const int lj = (tid & 15) * 4;   // 4 hidden units per loader thread
    const float* inb = g_seq0 + (size_t)(b0 + lr) * HH + lj;
    {
        float4 a = *reinterpret_cast<const float4*>(inb);
#pragma unroll
        for (int i = 0; i < 4; ++i)
            *reinterpret_cast<float2*>(sin + (lj + i) * 64 + lr * 2) =
                make_float2((&a.x)[i], (&a.x)[i]);
    }
    __syncthreads();
    {
        float4 bv = *reinterpret_cast<const float4*>(sb + hb4);
        b_if = pk22(bv.x, bv.y);
        b_go = pk22(bv.z, bv.w);
    }
    cst[0] = cst[1] = cst[2] = cst[3] = 0.f;
    buf = 0;

    for (int t = 0; t < TT; ++t) {
        float4 pa = make_float4(0.f, 0.f, 0.f, 0.f);
        if (t + 1 < TT) pa = *reinterpret_cast<const float4*>(inb + (size_t)(t + 1) * (BB * HH));

        unsigned long long acc[8] = {b_if, b_go, b_if, b_go, b_if, b_go, b_if, b_go};
        gemm_dup<HH>(sin + buf * 4096, sWih, rb8, hb4, acc);
        gemm_dup<HH>(shT + buf * 4096, sWhh, rb8, hb4, acc);
        lstm_act4(acc, cst, hv);

        int nb = buf ^ 1;
        float* sh_n = shT + nb * 4096;
#pragma unroll
        for (int rr = 0; rr < 4; ++rr)
            *reinterpret_cast<float2*>(sh_n + cg * 64 + (rb4 + rr) * 2) = make_float2(hv[rr], hv[rr]);
        float* sx_n = sin + nb * 4096;
#pragma unroll
        for (int i = 0; i < 4; ++i)
            *reinterpret_cast<float2*>(sx_n + (lj + i) * 64 + lr * 2) =
                make_float2((&pa.x)[i], (&pa.x)[i]);
        __syncthreads();
        buf = nb;
    }
#pragma unroll
    for (int rr = 0; rr < 4; ++rr) {
        g_h1[(size_t)(b0 + rb4 + rr) * HH + cg] = hv[rr];
        g_c1[(size_t)(b0 + rb4 + rr) * HH + cg] = cst[rr];
    }
}

// ==================== kernel 2: decoder (2 layers + FC, 24 steps) ====================
__global__ void __launch_bounds__(THR, 1)
k_dec(const float* __restrict__ W0ih, const float* __restrict__ W0hh,
      const float* __restrict__ b0ih, const float* __restrict__ b0hh,
      const float* __restrict__ W1ih, const float* __restrict__ W1hh,
      const float* __restrict__ b1ih, const float* __restrict__ b1hh,
      const float* __restrict__ fcW, const float* __restrict__ fcb,
      float* __restrict__ out) {
    extern __shared__ float sm[];
    float* sW0ih = sm;                        // 8*256
    float* sW0hh = sW0ih + NT * 256;          // 64*256
    float* sW1ih = sW0hh + HH * 256;          // 64*256
    float* sW1hh = sW1ih + HH * 256;          // 64*256
    float* sb0   = sW1hh + HH * 256;          // 256
    float* sb1   = sb0 + 256;                 // 256
    float* sfcW  = sb1 + 256;                 // 64*8
    float* sfcb  = sfcW + HH * NT;            // 8
    float* sh0   = sfcb + 8;                  // 64*32
    float* sh1   = sh0 + HH * BT;             // 64*32
    float* spr   = sh1 + HH * BT;             // 8*32

    const int tid = threadIdx.x;
    const int rb4 = (tid & 7) * 4;
    const int cg  = tid >> 3;
    const int hb4 = cg * 4;
    const int b0  = blockIdx.x * BT;

    load_w(sW0ih, W0ih, NT, tid);
    load_w(sW0hh, W0hh, HH, tid);
    load_w(sW1ih, W1ih, HH, tid);
    load_w(sW1hh, W1hh, HH, tid);
    if (tid < 256) {
        int j = tid >> 2, g = tid & 3;
        sb0[tid] = b0ih[g * HH + j] + b0hh[g * HH + j];
        sb1[tid] = b1ih[g * HH + j] + b1hh[g * HH + j];
    }
    for (int idx = tid; idx < HH * NT; idx += THR) {
        int j = idx >> 3, m = idx & 7;
        sfcW[j * NT + m] = fcW[m * HH + j];
    }
    if (tid < NT) sfcb[tid] = fcb[tid];
    for (int idx = tid; idx < HH * BT; idx += THR) {
        int j = idx >> 5, r = idx & 31;
        sh0[idx] = g_h0[(size_t)(b0 + r) * HH + j];
        sh1[idx] = g_h1[(size_t)(b0 + r) * HH + j];
    }
    for (int idx = tid; idx < NT * BT; idx += THR) spr[idx] = 0.f;

    float cst0[4], cst1[4], hv0[4], hv1[4];
#pragma unroll
    for (int rr = 0; rr < 4; ++rr) {
        cst0[rr] = g_c0[(size_t)(b0 + rb4 + rr) * HH + cg];
        cst1[rr] = g_c1[(size_t)(b0 + rb4 + rr) * HH + cg];
    }
    __syncthreads();

    unsigned long long b0_if, b0_go, b1_if, b1_go;
    {
        float4 bv = *reinterpret_cast<const float4*>(sb0 + hb4);
        b0_if = pk22(bv.x, bv.y); b0_go = pk22(bv.z, bv.w);
        float4 bw = *reinterpret_cast<const float4*>(sb1 + hb4);
        b1_if = pk22(bw.x, bw.y); b1_go = pk22(bw.z, bw.w);
    }

    const int fr = (tid >> 3) & 31;
    const int fm = tid & 7;

    for (int s = 0; s < HOR; ++s) {
        // ---- decoder layer 0: input = previous prediction ----
        unsigned long long acc[8] = {b0_if, b0_go, b0_if, b0_go, b0_if, b0_go, b0_if, b0_go};
        gemm_nd<NT>(spr, sW0ih, rb4, hb4, acc);
        gemm_nd<HH>(sh0, sW0hh, rb4, hb4, acc);
        lstm_act4(acc, cst0, hv0);
        __syncthreads();
#pragma unroll
        for (int rr = 0; rr < 4; ++rr) sh0[cg * BT + rb4 + rr] = hv0[rr];
        __syncthreads();

        // ---- decoder layer 1: input = new h0 ----
        unsigned long long acc2[8] = {b1_if, b1_go, b1_if, b1_go, b1_if, b1_go, b1_if, b1_go};
        gemm_nd<HH>(sh0, sW1ih, rb4, hb4, acc2);
        gemm_nd<HH>(sh1, sW1hh, rb4, hb4, acc2);
        lstm_act4(acc2, cst1, hv1);
        __syncthreads();
#pragma unroll
        for (int rr = 0; rr < 4; ++rr) sh1[cg * BT + rb4 + rr] = hv1[rr];
        __syncthreads();

        // ---- FC: pred[r][m] = h1[r] . fcW[m] + fcb[m]  (first 256 threads) ----
        if (tid < 256) {
            float p = sfcb[fm];
#pragma unroll 8
            for (int j = 0; j < HH; ++j) p += sh1[j * BT + fr] * sfcW[j * NT + fm];
            out[(size_t)(b0 + fr) * (HOR * NT) + s * NT + fm] = p;
            spr[fm * BT + fr] = p;
        }
        __syncthreads();
    }
}

// ==================== launch ====================
extern "C" void kernel_launch(void* const* d_in, const int* in_sizes, int n_in,
                              void* d_out, int out_size) {
    const float* x      = (const float*)d_in[0];
    const float* eW0ih  = (const float*)d_in[1];
    const float* eW0hh  = (const float*)d_in[2];
    const float* eb0ih  = (const float*)d_in[3];
    const float* eb0hh  = (const float*)d_in[4];
    const float* eW1ih  = (const float*)d_in[5];
    const float* eW1hh  = (const float*)d_in[6];
    const float* eb1ih  = (const float*)d_in[7];
    const float* eb1hh  = (const float*)d_in[8];
    const float* dW0ih  = (const float*)d_in[9];
    const float* dW0hh  = (const float*)d_in[10];
    const float* db0ih  = (const float*)d_in[11];
    const float* db0hh  = (const float*)d_in[12];
    const float* dW1ih  = (const float*)d_in[13];
    const float* dW1hh  = (const float*)d_in[14];
    const float* db1ih  = (const float*)d_in[15];
    const float* db1hh  = (const float*)d_in[16];
    const float* fcW    = (const float*)d_in[17];
    const float* fcb    = (const float*)d_in[18];
    float* out = (float*)d_out;

    const int SM_ENC = (HH * 256 * 2 + 256 + 4 * HH * 64) * 4;   // 197,632 B
    const int SM_DEC = (NT * 256 + 3 * HH * 256 + 2 * 256 + HH * NT + 8 +
                        2 * HH * BT + NT * BT) * 4;              // 226,336 B

    cudaFuncSetAttribute(k_enc, cudaFuncAttributeMaxDynamicSharedMemorySize, SM_ENC);
    cudaFuncSetAttribute(k_dec, cudaFuncAttributeMaxDynamicSharedMemorySize, SM_DEC);

    k_enc<<<NCTA, THR, SM_ENC>>>(x, eW0ih, eW0hh, eb0ih, eb0hh,
                                 eW1ih, eW1hh, eb1ih, eb1hh);
    k_dec<<<NCTA, THR, SM_DEC>>>(dW0ih, dW0hh, db0ih, db0hh,
                                 dW1ih, dW1hh, db1ih, db1hh,
                                 fcW, fcb, out);
    (void)in_sizes; (void)n_in; (void)out_size;
}

// round 4
// speedup vs baseline: 2.9222x; 2.9222x over previous
#include <cuda_runtime.h>

// ---------------- problem constants ----------------
#define BB   4096
#define TT   168
#define NF   32
#define HH   64
#define NT   8
#define HOR  24
#define BT   32          // batch rows per CTA
#define NCTA (BB / BT)   // 128
#define THR  256
#define SSTR 36          // padded smem input-row stride (floats) -> conflict-free

// ---------------- scratch (device globals; no allocs allowed) ----------------
// g_seq0: [t][cta][unit][row]  (coalesced stores/loads)
__device__ float g_seq0[(size_t)TT * NCTA * HH * BT];
__device__ float g_h0[NCTA * HH * BT];   // [cta][unit][row]
__device__ float g_c0[NCTA * HH * BT];
__device__ float g_h1[NCTA * HH * BT];
__device__ float g_c1[NCTA * HH * BT];

// ---------------- packed f32x2 helpers (sm_100+) ----------------
__device__ __forceinline__ unsigned long long pk2(float a) {
    unsigned long long r;
    asm("mov.b64 %0, {%1, %1};" : "=l"(r) : "f"(a));
    return r;
}
__device__ __forceinline__ unsigned long long pk22(float a, float b) {
    unsigned long long r;
    asm("mov.b64 %0, {%1, %2};" : "=l"(r) : "f"(a), "f"(b));
    return r;
}
__device__ __forceinline__ void ffma2(unsigned long long& d, unsigned long long a, unsigned long long b) {
    asm("fma.rn.f32x2 %0, %1, %2, %0;" : "+l"(d) : "l"(a), "l"(b));
}
__device__ __forceinline__ float2 unpk2(unsigned long long v) {
    float2 r;
    asm("mov.b64 {%0, %1}, %2;" : "=f"(r.x), "=f"(r.y) : "l"(v));
    return r;
}

// fast activations (~1e-6 rel err)
__device__ __forceinline__ float sigf(float x) {
    return __fdividef(1.f, 1.f + __expf(-x));
}
__device__ __forceinline__ float tanhf_(float x) {
    float e = __expf(2.f * x);
    return 1.f - __fdividef(2.f, e + 1.f);
}

// ---------------- GEMM tile: acc[4 rows][2 units x (if,go)] += In^T * W ----------------
// sIn : [KDIM][SSTR]  (transposed inputs, padded stride 36 -> conflict-free float4 loads)
// sW  : [KDIM][256]   (transposed weights, gate-interleaved: col' = 4*j + gate)
template <int KDIM>
__device__ __forceinline__ void gemm36(const float* __restrict__ sIn,
                                       const float* __restrict__ sW,
                                       int rb4, int hb8,
                                       unsigned long long* __restrict__ acc) {
#pragma unroll 8
    for (int k = 0; k < KDIM; ++k) {
        float4 h4 = *reinterpret_cast<const float4*>(sIn + k * SSTR + rb4);
        ulonglong2 w01 = *reinterpret_cast<const ulonglong2*>(sW + k * 256 + hb8);
        ulonglong2 w23 = *reinterpret_cast<const ulonglong2*>(sW + k * 256 + hb8 + 4);
        unsigned long long hx = pk2(h4.x);
        unsigned long long hy = pk2(h4.y);
        unsigned long long hz = pk2(h4.z);
        unsigned long long hw = pk2(h4.w);
        ffma2(acc[0],  hx, w01.x); ffma2(acc[1],  hx, w01.y);
        ffma2(acc[2],  hx, w23.x); ffma2(acc[3],  hx, w23.y);
        ffma2(acc[4],  hy, w01.x); ffma2(acc[5],  hy, w01.y);
        ffma2(acc[6],  hy, w23.x); ffma2(acc[7],  hy, w23.y);
        ffma2(acc[8],  hz, w01.x); ffma2(acc[9],  hz, w01.y);
        ffma2(acc[10], hz, w23.x); ffma2(acc[11], hz, w23.y);
        ffma2(acc[12], hw, w01.x); ffma2(acc[13], hw, w01.y);
        ffma2(acc[14], hw, w23.x); ffma2(acc[15], hw, w23.y);
    }
}

__device__ __forceinline__ void init_acc(unsigned long long* acc,
                                         unsigned long long b_if0, unsigned long long b_go0,
                                         unsigned long long b_if1, unsigned long long b_go1) {
#pragma unroll
    for (int rr = 0; rr < 4; ++rr) {
        acc[rr * 4 + 0] = b_if0;
        acc[rr * 4 + 1] = b_go0;
        acc[rr * 4 + 2] = b_if1;
        acc[rr * 4 + 3] = b_go1;
    }
}

// LSTM gate math: 4 rows x 2 units. cst/hv indexed [u*4 + rr].
__device__ __forceinline__ void lstm_act(const unsigned long long* __restrict__ acc,
                                         float* __restrict__ cst, float* __restrict__ hv) {
#pragma unroll
    for (int u = 0; u < 2; ++u)
#pragma unroll
        for (int rr = 0; rr < 4; ++rr) {
            float2 iff = unpk2(acc[rr * 4 + 2 * u]);
            float2 go  = unpk2(acc[rr * 4 + 2 * u + 1]);
            float iv = sigf(iff.x);
            float fv = sigf(iff.y);
            float gv = tanhf_(go.x);
            float ov = sigf(go.y);
            float c = fv * cst[u * 4 + rr] + iv * gv;
            cst[u * 4 + rr] = c;
            hv[u * 4 + rr] = ov * tanhf_(c);
        }
}

// weight loader: dst[k*256 + (4j+g)] = src[(g*64+j)*K + k]
__device__ __forceinline__ void load_w(float* __restrict__ dst, const float* __restrict__ src,
                                       int K, int tid) {
    for (int idx = tid; idx < K * 256; idx += THR) {
        int k = idx >> 8, c = idx & 255, j = c >> 2, g = c & 3;
        dst[idx] = src[(g * HH + j) * K + k];
    }
}

// ==================== kernel 1: fused 2-layer encoder ====================
__global__ void __launch_bounds__(THR, 1)
k_enc(const float* __restrict__ x,
      const float* __restrict__ W0ih, const float* __restrict__ W0hh,
      const float* __restrict__ b0ih, const float* __restrict__ b0hh,
      const float* __restrict__ W1ih, const float* __restrict__ W1hh,
      const float* __restrict__ b1ih, const float* __restrict__ b1hh) {
    extern __shared__ float sm[];
    float* sWih = sm;                        // 64*256 (phase0 uses 32 rows)
    float* sWhh = sWih + HH * 256;           // 64*256
    float* sb   = sWhh + HH * 256;           // 256
    float* sx   = sb + 256;                  // 2 x 64*36 (phase0 uses 32 rows)
    float* shT  = sx + 2 * HH * SSTR;        // 2 x 64*36

    const int tid = threadIdx.x;
    const int rb4 = (tid & 7) * 4;           // rows rb4..rb4+3
    const int ug  = tid >> 3;                // unit group 0..31
    const int j0  = ug * 2;                  // units j0, j0+1
    const int hb8 = ug * 8;
    const int cta = blockIdx.x;
    const int b0  = cta * BT;

    float cst[8] = {0, 0, 0, 0, 0, 0, 0, 0};
    float hv[8];
    unsigned long long acc[16];
    unsigned long long b_if0, b_go0, b_if1, b_go1;

    // =================== phase 0: encoder layer 0 ===================
    load_w(sWih, W0ih, NF, tid);
    load_w(sWhh, W0hh, HH, tid);
    {
        int j = tid >> 2, g = tid & 3;
        sb[tid] = b0ih[g * HH + j] + b0hh[g * HH + j];
    }
    for (int i = tid; i < HH * SSTR; i += THR) shT[i] = 0.f;   // h(-1) = 0 (buf 0)

    // x loaders: lr = row 0..31, lf4 = 4 features
    const int lr  = tid >> 3;
    const int lf4 = (tid & 7) * 4;
    const float* xb = x + (size_t)(b0 + lr) * (TT * NF) + lf4;
    {   // preload x(0) -> buf0, x(1) -> buf1
        float4 p0 = *reinterpret_cast<const float4*>(xb);
        float4 p1 = *reinterpret_cast<const float4*>(xb + NF);
#pragma unroll
        for (int i = 0; i < 4; ++i) {
            sx[(lf4 + i) * SSTR + lr]              = (&p0.x)[i];
            sx[HH * SSTR + (lf4 + i) * SSTR + lr]  = (&p1.x)[i];
        }
    }
    __syncthreads();
    {
        float4 ba = *reinterpret_cast<const float4*>(sb + hb8);
        float4 bb = *reinterpret_cast<const float4*>(sb + hb8 + 4);
        b_if0 = pk22(ba.x, ba.y); b_go0 = pk22(ba.z, ba.w);
        b_if1 = pk22(bb.x, bb.y); b_go1 = pk22(bb.z, bb.w);
    }
    // acc = bias + x-part(0)
    init_acc(acc, b_if0, b_go0, b_if1, b_go1);
    gemm36<NF>(sx, sWih, rb4, hb8, acc);

    for (int t = 0; t < TT; ++t) {
        // prefetch x(t+2) early (global latency hidden under gemm)
        float4 pf = make_float4(0.f, 0.f, 0.f, 0.f);
        if (t + 2 < TT) pf = *reinterpret_cast<const float4*>(xb + (t + 2) * NF);

        // h-part gemm for step t
        gemm36<HH>(shT + (t & 1) * (HH * SSTR), sWhh, rb4, hb8, acc);
        lstm_act(acc, cst, hv);

        // x-part gemm for t+1 (independent of act -> overlaps MUFU chains)
        init_acc(acc, b_if0, b_go0, b_if1, b_go1);
        gemm36<NF>(sx + ((t + 1) & 1) * (HH * SSTR), sWih, rb4, hb8, acc);

        // store h(t) to g_seq0 [t][cta][unit][row]  (2x STG.128)
        {
            float* sq = g_seq0 + ((size_t)t * NCTA + cta) * (HH * BT);
            *reinterpret_cast<float4*>(sq + j0 * BT + rb4)       = *reinterpret_cast<float4*>(hv);
            *reinterpret_cast<float4*>(sq + (j0 + 1) * BT + rb4) = *reinterpret_cast<float4*>(hv + 4);
        }
        // stage h(t) for next step
        {
            float* shn = shT + ((t + 1) & 1) * (HH * SSTR);
#pragma unroll
            for (int u = 0; u < 2; ++u)
#pragma unroll
                for (int rr = 0; rr < 4; ++rr)
                    shn[(j0 + u) * SSTR + rb4 + rr] = hv[u * 4 + rr];
        }
        // stage x(t+2)
        {
            float* sxn = sx + (t & 1) * (HH * SSTR);
#pragma unroll
            for (int i = 0; i < 4; ++i)
                sxn[(lf4 + i) * SSTR + lr] = (&pf.x)[i];
        }
        __syncthreads();
    }
    {   // final state of layer 0
        float* h0p = g_h0 + (size_t)cta * (HH * BT);
        float* c0p = g_c0 + (size_t)cta * (HH * BT);
        *reinterpret_cast<float4*>(h0p + j0 * BT + rb4)       = *reinterpret_cast<float4*>(hv);
        *reinterpret_cast<float4*>(h0p + (j0 + 1) * BT + rb4) = *reinterpret_cast<float4*>(hv + 4);
        *reinterpret_cast<float4*>(c0p + j0 * BT + rb4)       = *reinterpret_cast<float4*>(cst);
        *reinterpret_cast<float4*>(c0p + (j0 + 1) * BT + rb4) = *reinterpret_cast<float4*>(cst + 4);
    }

    // =================== phase 1: encoder layer 1 ===================
    __syncthreads();    // everyone done with phase-0 weights / buffers
    load_w(sWih, W1ih, HH, tid);
    load_w(sWhh, W1hh, HH, tid);
    {
        int j = tid >> 2, g = tid & 3;
        sb[tid] = b1ih[g * HH + j] + b1hh[g * HH + j];
    }
    for (int i = tid; i < HH * SSTR; i += THR) shT[i] = 0.f;

    // seq0 loaders: jL = unit 0..63, r0 = 8 rows
    const int jL = tid >> 2;
    const int r0 = (tid & 3) * 8;
    const float* sq0 = g_seq0 + (size_t)cta * (HH * BT) + jL * BT + r0;
    {   // preload seq0(0) -> buf0, seq0(1) -> buf1
        float4 a0 = *reinterpret_cast<const float4*>(sq0);
        float4 a1 = *reinterpret_cast<const float4*>(sq0 + 4);
        const float* s1 = sq0 + (size_t)NCTA * (HH * BT);
        float4 b0v = *reinterpret_cast<const float4*>(s1);
        float4 b1v = *reinterpret_cast<const float4*>(s1 + 4);
        *reinterpret_cast<float4*>(sx + jL * SSTR + r0)               = a0;
        *reinterpret_cast<float4*>(sx + jL * SSTR + r0 + 4)           = a1;
        *reinterpret_cast<float4*>(sx + HH * SSTR + jL * SSTR + r0)     = b0v;
        *reinterpret_cast<float4*>(sx + HH * SSTR + jL * SSTR + r0 + 4) = b1v;
    }
    __syncthreads();
    {
        float4 ba = *reinterpret_cast<const float4*>(sb + hb8);
        float4 bb = *reinterpret_cast<const float4*>(sb + hb8 + 4);
        b_if0 = pk22(ba.x, ba.y); b_go0 = pk22(ba.z, ba.w);
        b_if1 = pk22(bb.x, bb.y); b_go1 = pk22(bb.z, bb.w);
    }
#pragma unroll
    for (int i = 0; i < 8; ++i) cst[i] = 0.f;
    init_acc(acc, b_if0, b_go0, b_if1, b_go1);
    gemm36<HH>(sx, sWih, rb4, hb8, acc);

    for (int t = 0; t < TT; ++t) {
        float4 pfa = make_float4(0.f, 0.f, 0.f, 0.f);
        float4 pfb = make_float4(0.f, 0.f, 0.f, 0.f);
        if (t + 2 < TT) {
            const float* s2 = sq0 + (size_t)(t + 2) * NCTA * (HH * BT);
            pfa = *reinterpret_cast<const float4*>(s2);
            pfb = *reinterpret_cast<const float4*>(s2 + 4);
        }

        gemm36<HH>(shT + (t & 1) * (HH * SSTR), sWhh, rb4, hb8, acc);
        lstm_act(acc, cst, hv);

        init_acc(acc, b_if0, b_go0, b_if1, b_go1);
        gemm36<HH>(sx + ((t + 1) & 1) * (HH * SSTR), sWih, rb4, hb8, acc);

        {
            float* shn = shT + ((t + 1) & 1) * (HH * SSTR);
#pragma unroll
            for (int u = 0; u < 2; ++u)
#pragma unroll
                for (int rr = 0; rr < 4; ++rr)
                    shn[(j0 + u) * SSTR + rb4 + rr] = hv[u * 4 + rr];
        }
        {
            float* sxn = sx + (t & 1) * (HH * SSTR);
            *reinterpret_cast<float4*>(sxn + jL * SSTR + r0)     = pfa;
            *reinterpret_cast<float4*>(sxn + jL * SSTR + r0 + 4) = pfb;
        }
        __syncthreads();
    }
    {   // final state of layer 1
        float* h1p = g_h1 + (size_t)cta * (HH * BT);
        float* c1p = g_c1 + (size_t)cta * (HH * BT);
        *reinterpret_cast<float4*>(h1p + j0 * BT + rb4)       = *reinterpret_cast<float4*>(hv);
        *reinterpret_cast<float4*>(h1p + (j0 + 1) * BT + rb4) = *reinterpret_cast<float4*>(hv + 4);
        *reinterpret_cast<float4*>(c1p + j0 * BT + rb4)       = *reinterpret_cast<float4*>(cst);
        *reinterpret_cast<float4*>(c1p + (j0 + 1) * BT + rb4) = *reinterpret_cast<float4*>(cst + 4);
    }
}

// ==================== kernel 2: decoder (2 layers + FC, 24 steps) ====================
__global__ void __launch_bounds__(THR, 1)
k_dec(const float* __restrict__ W0ih, const float* __restrict__ W0hh,
      const float* __restrict__ b0ih, const float* __restrict__ b0hh,
      const float* __restrict__ W1ih, const float* __restrict__ W1hh,
      const float* __restrict__ b1ih, const float* __restrict__ b1hh,
      const float* __restrict__ fcW, const float* __restrict__ fcb,
      float* __restrict__ out) {
    extern __shared__ float sm[];
    float* sW0ih = sm;                         // 8*256
    float* sW0hh = sW0ih + NT * 256;           // 64*256
    float* sW1ih = sW0hh + HH * 256;           // 64*256
    float* sW1hh = sW1ih + HH * 256;           // 64*256
    float* sb0   = sW1hh + HH * 256;           // 256
    float* sb1   = sb0 + 256;                  // 256
    float* sfcW  = sb1 + 256;                  // 64*8  [j][m]
    float* sfcb  = sfcW + HH * NT;             // 8
    float* sh0   = sfcb + 8;                   // 64*36
    float* sh1   = sh0 + HH * SSTR;            // 64*36
    float* spr   = sh1 + HH * SSTR;            // 8*36

    const int tid = threadIdx.x;
    const int rb4 = (tid & 7) * 4;
    const int ug  = tid >> 3;
    const int j0  = ug * 2;
    const int hb8 = ug * 8;
    const int cta = blockIdx.x;
    const int b0  = cta * BT;

    load_w(sW0ih, W0ih, NT, tid);
    load_w(sW0hh, W0hh, HH, tid);
    load_w(sW1ih, W1ih, HH, tid);
    load_w(sW1hh, W1hh, HH, tid);
    {
        int j = tid >> 2, g = tid & 3;
        sb0[tid] = b0ih[g * HH + j] + b0hh[g * HH + j];
        sb1[tid] = b1ih[g * HH + j] + b1hh[g * HH + j];
    }
    for (int idx = tid; idx < HH * NT; idx += THR) {
        int j = idx >> 3, m = idx & 7;
        sfcW[j * NT + m] = fcW[m * HH + j];
    }
    if (tid < NT) sfcb[tid] = fcb[tid];

    // load h states [cta][unit][row] -> stride-36 smem
    {
        const int jL = tid >> 2;
        const int r0 = (tid & 3) * 8;
        const float* h0p = g_h0 + (size_t)cta * (HH * BT) + jL * BT + r0;
        const float* h1p = g_h1 + (size_t)cta * (HH * BT) + jL * BT + r0;
        *reinterpret_cast<float4*>(sh0 + jL * SSTR + r0)     = *reinterpret_cast<const float4*>(h0p);
        *reinterpret_cast<float4*>(sh0 + jL * SSTR + r0 + 4) = *reinterpret_cast<const float4*>(h0p + 4);
        *reinterpret_cast<float4*>(sh1 + jL * SSTR + r0)     = *reinterpret_cast<const float4*>(h1p);
        *reinterpret_cast<float4*>(sh1 + jL * SSTR + r0 + 4) = *reinterpret_cast<const float4*>(h1p + 4);
    }
    for (int idx = tid; idx < NT * SSTR; idx += THR) spr[idx] = 0.f;

    float cst0[8], cst1[8], hv0[8], hv1[8];
    {
        const float* c0p = g_c0 + (size_t)cta * (HH * BT);
        const float* c1p = g_c1 + (size_t)cta * (HH * BT);
        *reinterpret_cast<float4*>(cst0)     = *reinterpret_cast<const float4*>(c0p + j0 * BT + rb4);
        *reinterpret_cast<float4*>(cst0 + 4) = *reinterpret_cast<const float4*>(c0p + (j0 + 1) * BT + rb4);
        *reinterpret_cast<float4*>(cst1)     = *reinterpret_cast<const float4*>(c1p + j0 * BT + rb4);
        *reinterpret_cast<float4*>(cst1 + 4) = *reinterpret_cast<const float4*>(c1p + (j0 + 1) * BT + rb4);
    }
    __syncthreads();

    unsigned long long b0_if0, b0_go0, b0_if1, b0_go1;
    unsigned long long b1_if0, b1_go0, b1_if1, b1_go1;
    {
        float4 a = *reinterpret_cast<const float4*>(sb0 + hb8);
        float4 b = *reinterpret_cast<const float4*>(sb0 + hb8 + 4);
        b0_if0 = pk22(a.x, a.y); b0_go0 = pk22(a.z, a.w);
        b0_if1 = pk22(b.x, b.y); b0_go1 = pk22(b.z, b.w);
        float4 c = *reinterpret_cast<const float4*>(sb1 + hb8);
        float4 d = *reinterpret_cast<const float4*>(sb1 + hb8 + 4);
        b1_if0 = pk22(c.x, c.y); b1_go0 = pk22(c.z, c.w);
        b1_if1 = pk22(d.x, d.y); b1_go1 = pk22(d.z, d.w);
    }

    const int fr = tid & 31;     // FC: row
    const int fm = tid >> 5;     // FC: target 0..7

    unsigned long long acc[16];

    for (int s = 0; s < HOR; ++s) {
        // ---- decoder layer 0 ----
        init_acc(acc, b0_if0, b0_go0, b0_if1, b0_go1);
        gemm36<NT>(spr, sW0ih, rb4, hb8, acc);
        gemm36<HH>(sh0, sW0hh, rb4, hb8, acc);
        lstm_act(acc, cst0, hv0);
        __syncthreads();
#pragma unroll
        for (int u = 0; u < 2; ++u)
#pragma unroll
            for (int rr = 0; rr < 4; ++rr)
                sh0[(j0 + u) * SSTR + rb4 + rr] = hv0[u * 4 + rr];
        __syncthreads();

        // ---- decoder layer 1 ----
        init_acc(acc, b1_if0, b1_go0, b1_if1, b1_go1);
        gemm36<HH>(sh0, sW1ih, rb4, hb8, acc);
        gemm36<HH>(sh1, sW1hh, rb4, hb8, acc);
        lstm_act(acc, cst1, hv1);
        __syncthreads();
#pragma unroll
        for (int u = 0; u < 2; ++u)
#pragma unroll
            for (int rr = 0; rr < 4; ++rr)
                sh1[(j0 + u) * SSTR + rb4 + rr] = hv1[u * 4 + rr];
        __syncthreads();

        // ---- FC: pred[r][m] = h1[r] . fcW[m] + fcb[m] ----
        {
            float p = sfcb[fm];
#pragma unroll 8
            for (int j = 0; j < HH; ++j) p += sh1[j * SSTR + fr] * sfcW[j * NT + fm];
            out[(size_t)(b0 + fr) * (HOR * NT) + s * NT + fm] = p;
            spr[fm * SSTR + fr] = p;
        }
        __syncthreads();
    }
}

// ==================== launch ====================
extern "C" void kernel_launch(void* const* d_in, const int* in_sizes, int n_in,
                              void* d_out, int out_size) {
    const float* x      = (const float*)d_in[0];
    const float* eW0ih  = (const float*)d_in[1];
    const float* eW0hh  = (const float*)d_in[2];
    const float* eb0ih  = (const float*)d_in[3];
    const float* eb0hh  = (const float*)d_in[4];
    const float* eW1ih  = (const float*)d_in[5];
    const float* eW1hh  = (const float*)d_in[6];
    const float* eb1ih  = (const float*)d_in[7];
    const float* eb1hh  = (const float*)d_in[8];
    const float* dW0ih  = (const float*)d_in[9];
    const float* dW0hh  = (const float*)d_in[10];
    const float* db0ih  = (const float*)d_in[11];
    const float* db0hh  = (const float*)d_in[12];
    const float* dW1ih  = (const float*)d_in[13];
    const float* dW1hh  = (const float*)d_in[14];
    const float* db1ih  = (const float*)d_in[15];
    const float* db1hh  = (const float*)d_in[16];
    const float* fcW    = (const float*)d_in[17];
    const float* fcb    = (const float*)d_in[18];
    float* out = (float*)d_out;

    const int SM_ENC = (2 * HH * 256 + 256 + 4 * HH * SSTR) * 4;           // 169,984 B
    const int SM_DEC = (NT * 256 + 3 * HH * 256 + 2 * 256 + HH * NT + 8 +
                        2 * HH * SSTR + NT * SSTR) * 4;                    // ~221 KB

    cudaFuncSetAttribute(k_enc, cudaFuncAttributeMaxDynamicSharedMemorySize, SM_ENC);
    cudaFuncSetAttribute(k_dec, cudaFuncAttributeMaxDynamicSharedMemorySize, SM_DEC);

    k_enc<<<NCTA, THR, SM_ENC>>>(x, eW0ih, eW0hh, eb0ih, eb0hh,
                                 eW1ih, eW1hh, eb1ih, eb1hh);
    k_dec<<<NCTA, THR, SM_DEC>>>(dW0ih, dW0hh, db0ih, db0hh,
                                 dW1ih, dW1hh, db1ih, db1hh,
                                 fcW, fcb, out);
    (void)in_sizes; (void)n_in; (void)out_size;
}